// round 6
// baseline (speedup 1.0000x reference)
#include <cuda_runtime.h>
#include <cuda_bf16.h>
#include <math_constants.h>

// Problem constants
#define NB   16
#define NC   1024
#define NT   16
#define NP   360          // H*W = 12*30
#define NK   120          // top-k
#define ROWS 482          // 1 + 120 + 1 + 360
#define TSTRIDE ((size_t)NT * NP)   // 5760 floats between consecutive c

// Block-role layout (dispatch is monotone in bid -> producers precede consumers)
#define BID_SCORE0 0
#define BID_SORT0  512
#define BID_COPY1  528
#define BID_COPY0  2064
#define GRID_TOTAL 3600

// Scratch (no device allocation allowed -> __device__ globals)
__device__ __align__(16) float g_spart[NB][64][NP];  // 5.9 MB
__device__ int g_posmap[NB][NP];
__device__ int g_cnt[NB * 32];    // per-b score-block counter (128B padded)
__device__ int g_flag[NB * 32];   // per-b sort-done flag      (128B padded)

__global__ void k_init()
{
    if (threadIdx.x < NB) {
        g_cnt[threadIdx.x * 32]  = 0;
        g_flag[threadIdx.x * 32] = 0;
    }
}

// ---------------------------------------------------------------------------
// transpose-tile helpers (32c x 128p, float4 both gmem sides, conflict-free
// component-split smem: tiles[j][c*33+pq] holds x[c][4*pq+j])
// ---------------------------------------------------------------------------
__device__ __forceinline__ void tile_load(float* tiles, const float* xbase,
                                          int pbase, int tid)
{
    #pragma unroll
    for (int i = 0; i < 4; ++i) {
        const int s  = tid + 256 * i;
        const int cl = s >> 5;           // 0..31
        const int pq = s & 31;           // 0..31
        const int p  = pbase + pq * 4;
        if (p < NP) {
            const float4 v = *reinterpret_cast<const float4*>(
                xbase + (size_t)cl * TSTRIDE + p);
            const int idx = cl * 33 + pq;
            tiles[0 * 1057 + idx] = v.x;
            tiles[1 * 1057 + idx] = v.y;
            tiles[2 * 1057 + idx] = v.z;
            tiles[3 * 1057 + idx] = v.w;
        }
    }
}

__device__ __forceinline__ void tile_store(const float* tiles, float* out,
                                           size_t obase, int ct, int pbase,
                                           int tid, int b, bool use_posmap)
{
    #pragma unroll
    for (int i = 0; i < 4; ++i) {
        const int s  = tid + 256 * i;
        const int cq = s & 7;            // 0..7
        const int pl = s >> 3;           // 0..127
        const int pg = pbase + pl;
        if (pg < NP) {
            const int row = use_posmap ? g_posmap[b][pg] : (122 + pg);
            if (row >= 0) {
                const int j  = pl & 3;
                const int pq = pl >> 2;
                float4 w;
                w.x = tiles[j * 1057 + (4 * cq + 0) * 33 + pq];
                w.y = tiles[j * 1057 + (4 * cq + 1) * 33 + pq];
                w.z = tiles[j * 1057 + (4 * cq + 2) * 33 + pq];
                w.w = tiles[j * 1057 + (4 * cq + 3) * 33 + pq];
                *reinterpret_cast<float4*>(
                    out + obase + (size_t)row * NC + ct * 32 + cq * 4) = w;
            }
        }
    }
}

// ---------------------------------------------------------------------------
// Fused kernel: scores | per-b sort | frame-1 copy | frame-0 gather copy,
// sequenced by device-scope flags, overlapped via block-role heterogeneity.
// ---------------------------------------------------------------------------
__global__ void __launch_bounds__(256, 3) k_fused(const float* __restrict__ x,
                                                  const float* __restrict__ cls,
                                                  float* __restrict__ out)
{
    __shared__ __align__(16) float sbuf[4 * 1057];   // 16.5 KB, role-dependent
    const int bid = blockIdx.x;
    const int tid = threadIdx.x;

    if (bid < BID_SORT0) {
        // ================= scores =================
        // block (b, cs): 32 c's = 2 halves of 16; 180 active threads.
        const int b  = bid >> 5;
        const int cs = bid & 31;
        if (tid < 180) {
            const int half  = tid / 90;
            const int pq    = tid - half * 90;
            const int cbase = cs * 32 + half * 16;
            const float*  wp = cls + b * (NT * NC) + cbase;     // t=0 cls
            const float4* xp = reinterpret_cast<const float4*>(
                x + ((size_t)b * NC + cbase) * TSTRIDE) + pq;   // t=0

            float4 acc = make_float4(0.f, 0.f, 0.f, 0.f);
            #pragma unroll
            for (int batch = 0; batch < 2; ++batch) {
                float4 v[8];
                float  w[8];
                #pragma unroll
                for (int j = 0; j < 8; ++j)
                    v[j] = xp[(size_t)(batch * 8 + j) * (TSTRIDE / 4)];
                #pragma unroll
                for (int j = 0; j < 8; ++j)
                    w[j] = __ldg(wp + batch * 8 + j);
                #pragma unroll
                for (int j = 0; j < 8; ++j) {
                    acc.x = fmaf(w[j], v[j].x, acc.x);
                    acc.y = fmaf(w[j], v[j].y, acc.y);
                    acc.z = fmaf(w[j], v[j].z, acc.z);
                    acc.w = fmaf(w[j], v[j].w, acc.w);
                }
            }
            *reinterpret_cast<float4*>(&g_spart[b][cs * 2 + half][pq * 4]) = acc;
        }
        __threadfence();
        __syncthreads();
        if (tid == 0) atomicAdd(&g_cnt[b * 32], 1);   // release
    }
    else if (bid < BID_COPY1) {
        // ================= per-b sort =================
        const int b = bid - BID_SORT0;
        float* sv = sbuf;                                    // [512]
        int*   si = reinterpret_cast<int*>(sbuf + 512);      // [512]

        if (tid == 0) {
            while (*((volatile int*)&g_cnt[b * 32]) < 32) __nanosleep(64);
        }
        __syncthreads();
        __threadfence();   // acquire: g_spart writes now visible

        for (int e = tid; e < 512; e += 256) {
            float vsum = -CUDART_INF_F;
            if (e < NP) {
                float a0 = 0.f, a1 = 0.f, a2 = 0.f, a3 = 0.f;
                #pragma unroll
                for (int k = 0; k < 64; k += 4) {
                    a0 += g_spart[b][k + 0][e];
                    a1 += g_spart[b][k + 1][e];
                    a2 += g_spart[b][k + 2][e];
                    a3 += g_spart[b][k + 3][e];
                }
                vsum = (a0 + a1) + (a2 + a3);
            }
            sv[e] = vsum;
            si[e] = e;
        }
        __syncthreads();

        // bitonic sort 512 (desc score, asc idx tiebreak = lax.top_k semantics)
        for (int k = 2; k <= 512; k <<= 1) {
            for (int j = k >> 1; j > 0; j >>= 1) {
                const int l = 2 * tid - (tid & (j - 1));   // l & j == 0
                const int m = l | j;
                const float a = sv[l], c = sv[m];
                const int   ia = si[l], ic = si[m];
                const bool a_after = (a < c) || (a == c && ia > ic);
                const bool dir_desc = ((l & k) == 0);
                if (dir_desc ? a_after : !a_after) {
                    sv[l] = c; sv[m] = a; si[l] = ic; si[m] = ia;
                }
                __syncthreads();
            }
        }

        for (int p = tid; p < NP; p += 256) g_posmap[b][p] = -1;
        __syncthreads();
        if (tid < NK) g_posmap[b][si[tid]] = 1 + tid;

        // cls rows: row 0 = cls[b,0,:], row 121 = cls[b,1,:]
        const size_t obase = (size_t)b * ROWS * NC;
        const float4* c4 = reinterpret_cast<const float4*>(cls + (size_t)b * NT * NC);
        float4* o4 = reinterpret_cast<float4*>(out + obase);
        for (int c = tid; c < NC / 4; c += 256) {
            o4[c]                = c4[c];
            o4[121 * (NC/4) + c] = c4[(NC/4) + c];
        }

        __threadfence();
        __syncthreads();
        if (tid == 0) atomicExch(&g_flag[b * 32], 1);  // release
    }
    else if (bid < BID_COPY0) {
        // ================= frame-1 transpose copy (independent) =============
        const int idx = bid - BID_COPY1;
        const int ct  = idx & 31;
        const int rem = idx >> 5;
        const int pt  = rem % 3;
        const int b   = rem / 3;

        const float* xbase = x + ((size_t)b * NC + ct * 32) * TSTRIDE + NP; // t=1
        const int pbase = pt * 128;

        tile_load(sbuf, xbase, pbase, tid);
        __syncthreads();
        tile_store(sbuf, out, (size_t)b * ROWS * NC, ct, pbase, tid, b, false);
    }
    else {
        // ================= frame-0 selective transpose copy =================
        const int idx = bid - BID_COPY0;
        const int ct  = idx & 31;
        const int rem = idx >> 5;
        const int pt  = rem % 3;
        const int b   = rem / 3;

        const float* xbase = x + ((size_t)b * NC + ct * 32) * TSTRIDE;      // t=0
        const int pbase = pt * 128;

        // load first (hides the sort wait under the tile's DRAM/L2 latency)
        tile_load(sbuf, xbase, pbase, tid);

        if (tid == 0) {
            while (*((volatile int*)&g_flag[b * 32]) == 0) __nanosleep(128);
        }
        __syncthreads();
        __threadfence();   // acquire: posmap visible

        tile_store(sbuf, out, (size_t)b * ROWS * NC, ct, pbase, tid, b, true);
    }
}

// ---------------------------------------------------------------------------
extern "C" void kernel_launch(void* const* d_in, const int* in_sizes, int n_in,
                              void* d_out, int out_size)
{
    const float* x   = (const float*)d_in[0];   // [16,1024,16,12,30]
    const float* cls = (const float*)d_in[1];   // [16,16,1024]
    float* out = (float*)d_out;                 // [16,482,1024]

    k_init<<<1, 32>>>();
    k_fused<<<GRID_TOTAL, 256>>>(x, cls, out);
}

// round 8
// speedup vs baseline: 1.0986x; 1.0986x over previous
#include <cuda_runtime.h>
#include <cuda_bf16.h>
#include <math_constants.h>
#include <cstdint>

// Problem constants
#define NB   16
#define NC   1024
#define NT   16
#define NP   360          // H*W = 12*30
#define NK   120          // top-k
#define ROWS 482          // 1 + 120 + 1 + 360
#define CSPLIT 64
#define CCHUNK (NC / CSPLIT)        // 16 c per score block
#define TSTRIDE ((size_t)NT * NP)   // 5760 floats between consecutive c

// Scratch (no device allocation allowed -> __device__ globals)
__device__ __align__(16) float g_spart[NB][CSPLIT][NP];   // 1.5 MB
__device__ int g_posmap[NB][NP];

// ---------------------------------------------------------------------------
// K1: partial dots via cp.async staging.
// grid (16, 64) = 1024 blocks, 256 threads.
// Each block copies its 16-c x 360-p slab (23 KB) to smem with LDGSTS
// (no register landing -> full 23 KB in flight per block, ~7 blocks/SM),
// then 90 threads compute float4 partial dots from smem.
// ---------------------------------------------------------------------------
__global__ void __launch_bounds__(256) k_scores(const float* __restrict__ x,
                                                const float* __restrict__ cls)
{
    __shared__ __align__(16) float xs[CCHUNK * NP];   // 23040 B
    __shared__ float cls_s[CCHUNK];

    const int b   = blockIdx.x;
    const int cs  = blockIdx.y;
    const int tid = threadIdx.x;

    const float* xbase = x + ((size_t)b * NC + (size_t)cs * CCHUNK) * TSTRIDE; // t=0
    const unsigned int s_dst = (unsigned int)__cvta_generic_to_shared(xs);

    // issue all 1440 16-byte async copies (q = c*90 + off -> smem contiguous)
    for (int q = tid; q < CCHUNK * (NP / 4); q += 256) {
        const int c   = q / (NP / 4);
        const int off = q - c * (NP / 4);
        const float* src = xbase + (size_t)c * TSTRIDE + off * 4;
        asm volatile("cp.async.cg.shared.global [%0], [%1], 16;\n"
                     :: "r"(s_dst + q * 16), "l"(src));
    }
    if (tid < CCHUNK)
        cls_s[tid] = cls[b * (NT * NC) + cs * CCHUNK + tid];   // t=0 cls

    asm volatile("cp.async.commit_group;\ncp.async.wait_group 0;\n" ::: "memory");
    __syncthreads();

    if (tid < NP / 4) {   // 90 active p-quads
        float4 acc = make_float4(0.f, 0.f, 0.f, 0.f);
        #pragma unroll
        for (int c = 0; c < CCHUNK; ++c) {
            const float4 v = *reinterpret_cast<const float4*>(&xs[c * NP + tid * 4]);
            const float  w = cls_s[c];
            acc.x = fmaf(w, v.x, acc.x);
            acc.y = fmaf(w, v.y, acc.y);
            acc.z = fmaf(w, v.z, acc.z);
            acc.w = fmaf(w, v.w, acc.w);
        }
        *reinterpret_cast<float4*>(&g_spart[b][cs][tid * 4]) = acc;
    }
}

// ---------------------------------------------------------------------------
// K2 (fused): heterogeneous grid, 256 threads.
//   blocks 0..15       : per-b reduce + bitonic sort 512 (desc score, asc idx
//                        tiebreak = lax.top_k semantics), posmap, cls rows.
//   blocks 16..16+1535 : frame-1 transpose copy (independent of sort),
//                        32c x 128p tiles, float4 both gmem sides,
//                        conflict-free component-split smem.
// The ~3us sort hides under the ~7us frame-1 stream.
// ---------------------------------------------------------------------------
__global__ void __launch_bounds__(256) k_mid(const float* __restrict__ x,
                                             const float* __restrict__ cls,
                                             float* __restrict__ out)
{
    __shared__ float sv[512];
    __shared__ int   si[512];
    __shared__ float tiles[4][1057];    // stride 1057 == 1 (mod 32)

    const int tid = threadIdx.x;

    if (blockIdx.x < NB) {
        // ---------------- sort path ----------------
        const int b = blockIdx.x;

        for (int e = tid; e < 512; e += 256) {
            float vsum = -CUDART_INF_F;
            if (e < NP) {
                float a0 = 0.f, a1 = 0.f, a2 = 0.f, a3 = 0.f;
                #pragma unroll
                for (int k = 0; k < CSPLIT; k += 4) {
                    a0 += g_spart[b][k + 0][e];
                    a1 += g_spart[b][k + 1][e];
                    a2 += g_spart[b][k + 2][e];
                    a3 += g_spart[b][k + 3][e];
                }
                vsum = (a0 + a1) + (a2 + a3);
            }
            sv[e] = vsum;
            si[e] = e;
        }
        __syncthreads();

        // bitonic: 256 threads, one compare-exchange pair per substage
        for (int k = 2; k <= 512; k <<= 1) {
            for (int j = k >> 1; j > 0; j >>= 1) {
                const int l = 2 * tid - (tid & (j - 1));   // l & j == 0
                const int m = l | j;
                const float a = sv[l], c = sv[m];
                const int   ia = si[l], ic = si[m];
                const bool a_after = (a < c) || (a == c && ia > ic);
                const bool dir_desc = ((l & k) == 0);
                if (dir_desc ? a_after : !a_after) {
                    sv[l] = c; sv[m] = a; si[l] = ic; si[m] = ia;
                }
                __syncthreads();
            }
        }

        for (int p = tid; p < NP; p += 256) g_posmap[b][p] = -1;
        __syncthreads();
        if (tid < NK) g_posmap[b][si[tid]] = 1 + tid;

        // cls rows: row 0 = cls[b,0,:], row 121 = cls[b,1,:]
        const size_t obase = (size_t)b * ROWS * NC;
        const float4* c4 = reinterpret_cast<const float4*>(cls + (size_t)b * NT * NC);
        float4* o4 = reinterpret_cast<float4*>(out + obase);
        for (int c = tid; c < NC / 4; c += 256) {
            o4[c]                = c4[c];               // row 0   (t=0 cls)
            o4[121 * (NC/4) + c] = c4[(NC/4) + c];      // row 121 (t=1 cls)
        }
    } else {
        // ---------------- frame-1 copy path ----------------
        const int bid = blockIdx.x - NB;     // 0..1535
        const int ct  = bid & 31;            // c tile of 32
        const int rem = bid >> 5;
        const int pt  = rem % 3;             // p tile of 128
        const int b   = rem / 3;             // 0..15

        const float* xbase = x + (size_t)(b * NC + ct * 32) * TSTRIDE + NP; // t=1
        const int pbase = pt * 128;

        #pragma unroll
        for (int i = 0; i < 4; ++i) {
            const int s  = tid + 256 * i;
            const int cl = s >> 5;           // 0..31
            const int pq = s & 31;           // 0..31
            const int p  = pbase + pq * 4;
            if (p < NP) {
                const float4 v = *reinterpret_cast<const float4*>(
                    xbase + (size_t)cl * TSTRIDE + p);
                const int idx = cl * 33 + pq;
                tiles[0][idx] = v.x;
                tiles[1][idx] = v.y;
                tiles[2][idx] = v.z;
                tiles[3][idx] = v.w;
            }
        }
        __syncthreads();

        const size_t obase = (size_t)b * ROWS * NC;
        #pragma unroll
        for (int i = 0; i < 4; ++i) {
            const int s  = tid + 256 * i;
            const int cq = s & 7;            // 0..7
            const int pl = s >> 3;           // 0..127
            const int pg = pbase + pl;
            if (pg < NP) {
                const int row = 122 + pg;
                const int j  = pl & 3;
                const int pq = pl >> 2;
                float4 w;
                w.x = tiles[j][(4 * cq + 0) * 33 + pq];
                w.y = tiles[j][(4 * cq + 1) * 33 + pq];
                w.z = tiles[j][(4 * cq + 2) * 33 + pq];
                w.w = tiles[j][(4 * cq + 3) * 33 + pq];
                *reinterpret_cast<float4*>(
                    out + obase + (size_t)row * NC + ct * 32 + cq * 4) = w;
            }
        }
    }
}

// ---------------------------------------------------------------------------
// K3: frame-0 selective transpose copy (reads are L2-warm from K1/K2).
// grid (32, 3, 16), block 256. Only rows with posmap >= 0 are stored.
// ---------------------------------------------------------------------------
__global__ void __launch_bounds__(256) k_copy0(const float* __restrict__ x,
                                               float* __restrict__ out)
{
    const int ct = blockIdx.x;          // 0..31
    const int pt = blockIdx.y;          // 0..2
    const int b  = blockIdx.z;
    const int tid = threadIdx.x;

    __shared__ float tiles[4][1057];

    const float* xbase = x + (size_t)(b * NC + ct * 32) * TSTRIDE;  // t=0
    const int pbase = pt * 128;

    #pragma unroll
    for (int i = 0; i < 4; ++i) {
        const int s  = tid + 256 * i;
        const int cl = s >> 5;
        const int pq = s & 31;
        const int p  = pbase + pq * 4;
        if (p < NP) {
            const float4 v = *reinterpret_cast<const float4*>(
                xbase + (size_t)cl * TSTRIDE + p);
            const int idx = cl * 33 + pq;
            tiles[0][idx] = v.x;
            tiles[1][idx] = v.y;
            tiles[2][idx] = v.z;
            tiles[3][idx] = v.w;
        }
    }
    __syncthreads();

    const size_t obase = (size_t)b * ROWS * NC;
    #pragma unroll
    for (int i = 0; i < 4; ++i) {
        const int s  = tid + 256 * i;
        const int cq = s & 7;
        const int pl = s >> 3;
        const int pg = pbase + pl;
        if (pg < NP) {
            const int row = g_posmap[b][pg];
            if (row >= 0) {
                const int j  = pl & 3;
                const int pq = pl >> 2;
                float4 w;
                w.x = tiles[j][(4 * cq + 0) * 33 + pq];
                w.y = tiles[j][(4 * cq + 1) * 33 + pq];
                w.z = tiles[j][(4 * cq + 2) * 33 + pq];
                w.w = tiles[j][(4 * cq + 3) * 33 + pq];
                *reinterpret_cast<float4*>(
                    out + obase + (size_t)row * NC + ct * 32 + cq * 4) = w;
            }
        }
    }
}

// ---------------------------------------------------------------------------
extern "C" void kernel_launch(void* const* d_in, const int* in_sizes, int n_in,
                              void* d_out, int out_size)
{
    const float* x   = (const float*)d_in[0];   // [16,1024,16,12,30]
    const float* cls = (const float*)d_in[1];   // [16,16,1024]
    float* out = (float*)d_out;                 // [16,482,1024]

    k_scores<<<dim3(NB, CSPLIT), 256>>>(x, cls);
    k_mid<<<NB + 1536, 256>>>(x, cls, out);
    k_copy0<<<dim3(32, 3, NB), 256>>>(x, out);
}